// round 9
// baseline (speedup 1.0000x reference)
#include <cuda_runtime.h>
#include <cuda_fp16.h>
#include <cstdint>

typedef unsigned long long ull;

#define DIN   4096
#define NM    8
#define NH    512
#define NOUT  10

// fp16 pre-converted W1 diagonal blocks: [m][512 rows][512 k]
__device__ __half g_w1h[8u * 512u * 512u];

// ---- dynamic smem layout (bytes): 3-deep ring, 64-k chunks ----
#define STAGE_STRIDE 36864u      // A 128*144 + B 128*144
#define T_A          0u
#define T_B          18432u
#define OFF_HBUF     110592u     // 128 * 132 * 4 = 67584
#define HPITCH       132
#define OFF_W2       178176u     // 512*12*4 = 24576
#define OFF_B1       202752u     // 2048
#define SMEM_TOTAL   204800u

// named barriers: FULL 1..3, EMPTY 4..6, h 7..8
#define BFULL(s)   (1 + (s))
#define BEMPTY(s)  (4 + (s))
#define BHFULL     7
#define BHEMPTY    8
#define BAR_SYNC(id)   asm volatile("bar.sync %0, 256;"   :: "r"(id) : "memory")
#define BAR_ARRIVE(id) asm volatile("bar.arrive %0, 256;" :: "r"(id) : "memory")
#define MEMBAR_CTA()   asm volatile("membar.cta;" ::: "memory")

static __device__ __forceinline__ uint32_t smem_u32(const void* p) {
    uint32_t a;
    asm("{ .reg .u64 t; cvta.to.shared.u64 t, %1; cvt.u32.u64 %0, t; }"
        : "=r"(a) : "l"(p));
    return a;
}
static __device__ __forceinline__ void ldsm4(uint32_t* r, uint32_t addr) {
    asm volatile("ldmatrix.sync.aligned.m8n8.x4.shared.b16 {%0,%1,%2,%3}, [%4];"
                 : "=r"(r[0]), "=r"(r[1]), "=r"(r[2]), "=r"(r[3]) : "r"(addr));
}
static __device__ __forceinline__ void mma16816f(float* d, const uint32_t* a,
                                                 uint32_t b0, uint32_t b1) {
    asm volatile("mma.sync.aligned.m16n8k16.row.col.f32.f16.f16.f32 "
                 "{%0,%1,%2,%3}, {%4,%5,%6,%7}, {%8,%9}, {%0,%1,%2,%3};"
                 : "+f"(d[0]), "+f"(d[1]), "+f"(d[2]), "+f"(d[3])
                 : "r"(a[0]), "r"(a[1]), "r"(a[2]), "r"(a[3]), "r"(b0), "r"(b1));
}
static __device__ __forceinline__ void cp16(uint32_t dst, const void* src) {
    asm volatile("cp.async.cg.shared.global [%0], [%1], 16;"
                 :: "r"(dst), "l"(src) : "memory");
}
static __device__ __forceinline__ void cp_commit() {
    asm volatile("cp.async.commit_group;" ::: "memory");
}
static __device__ __forceinline__ void cp_wait1() {
    asm volatile("cp.async.wait_group 1;" ::: "memory");
}
static __device__ __forceinline__ void cp_wait0() {
    asm volatile("cp.async.wait_group 0;" ::: "memory");
}
static __device__ __forceinline__ ull packdup(float v) {
    ull r;
    asm("mov.b64 %0, {%1, %1};" : "=l"(r) : "r"(__float_as_uint(v)));
    return r;
}
static __device__ __forceinline__ void fma2(ull& d, ull a, ull b) {
    asm("fma.rn.f32x2 %0, %1, %2, %0;" : "+l"(d) : "l"(a), "l"(b));
}
static __device__ __forceinline__ void sts8(uint32_t addr, uint32_t a, uint32_t b) {
    asm volatile("st.shared.v2.b32 [%0], {%1,%2};" :: "r"(addr), "r"(a), "r"(b) : "memory");
}
static __device__ __forceinline__ void cvt4(float4 v, uint32_t& p01, uint32_t& p23) {
    __half2 a = __floats2half2_rn(v.x, v.y);
    __half2 b = __floats2half2_rn(v.z, v.w);
    p01 = *(uint32_t*)&a;
    p23 = *(uint32_t*)&b;
}

// ---------------- pre-pass: W1 diag blocks -> fp16 ----------------
__global__ __launch_bounds__(256)
void cvt_w1(const float* __restrict__ W1) {
    int g = blockIdx.x * 256 + threadIdx.x;
    int m = g >> 16;
    int rem = g & 65535;
    int r = rem >> 7;
    int c4 = rem & 127;
    float4 v = *(const float4*)(W1 + (size_t)(m * 512 + r) * DIN + m * 512 + c4 * 4);
    uint32_t p01, p23;
    cvt4(v, p01, p23);
    *(uint2*)(g_w1h + ((size_t)(m * 512 + r) * 512 + c4 * 4)) = make_uint2(p01, p23);
}

// ---------------- fused, warp-specialized fp16 kernel ----------------
__global__ __launch_bounds__(256, 1)
void fused_f16(const float* __restrict__ x,  const float* __restrict__ b1,
               const float* __restrict__ W2, const float* __restrict__ b2,
               float* __restrict__ y) {
    extern __shared__ char smem[];
    const uint32_t sb = smem_u32(smem);
    const int tid  = threadIdx.x;
    const int lane = tid & 31;
    const int m       = blockIdx.y;
    const int rowBase = blockIdx.x * 128;

    float* w2s  = (float*)(smem + OFF_W2);
    float* b1s  = (float*)(smem + OFF_B1);
    float* hbuf = (float*)(smem + OFF_HBUF);

    for (int i = tid; i < NH; i += 256) b1s[i] = b1[m * NH + i];
    for (int idx = tid; idx < NH * 12; idx += 256) {
        int c = idx / 12, o = idx - c * 12;
        w2s[idx] = (o < NOUT) ? W2[(size_t)(m * NOUT + o) * DIN + m * NH + c] : 0.f;
    }
    __syncthreads();

    if (tid < 128) {
        // ========== CONSUMERS: 4 warps, 64x64 tiles, 64-k chunks ==========
        const int wid = tid >> 5;
        const int wm = wid & 1;
        const int wn = wid >> 1;
        const uint32_t lmoff = (uint32_t)(lane & 15) * 144u + (uint32_t)(lane >> 4) * 16u;

        for (int p = 0; p < 4; p++) {
            float acc[4][8][4];
            #pragma unroll
            for (int i = 0; i < 4; i++)
                #pragma unroll
                for (int j = 0; j < 8; j++)
                    #pragma unroll
                    for (int q = 0; q < 4; q++) acc[i][j][q] = 0.f;

            for (int c = 0; c < 8; c++) {
                const int g = p * 8 + c;
                const int s = g % 3;
                BAR_SYNC(BFULL(s));
                const uint32_t base = sb + (uint32_t)s * STAGE_STRIDE;
                #pragma unroll
                for (int ks = 0; ks < 4; ks++) {
                    uint32_t af[4][4];
                    #pragma unroll
                    for (int i = 0; i < 4; i++) {
                        uint32_t off = (uint32_t)(wm * 64 + i * 16) * 144u + ks * 32u + lmoff;
                        ldsm4(af[i], base + T_A + off);
                    }
                    #pragma unroll
                    for (int jh = 0; jh < 2; jh++) {
                        uint32_t bf[4][2];
                        #pragma unroll
                        for (int jj = 0; jj < 2; jj++) {
                            uint32_t off = (uint32_t)(wn * 64 + jh * 32 + jj * 16) * 144u
                                         + ks * 32u + lmoff;
                            uint32_t rh[4];
                            ldsm4(rh, base + T_B + off);
                            bf[2 * jj][0] = rh[0];     bf[2 * jj][1] = rh[2];
                            bf[2 * jj + 1][0] = rh[1]; bf[2 * jj + 1][1] = rh[3];
                        }
                        #pragma unroll
                        for (int i = 0; i < 4; i++)
                            #pragma unroll
                            for (int j = 0; j < 4; j++)
                                mma16816f(acc[i][jh * 4 + j], af[i], bf[j][0], bf[j][1]);
                    }
                }
                BAR_ARRIVE(BEMPTY(s));
            }

            // epilogue: bias + relu -> hbuf
            BAR_SYNC(BHEMPTY);
            #pragma unroll
            for (int i = 0; i < 4; i++) {
                int r0 = wm * 64 + i * 16 + (lane >> 2);
                #pragma unroll
                for (int jc = 0; jc < 8; jc++) {
                    int c0 = wn * 64 + jc * 8 + 2 * (lane & 3);
                    float bb0 = b1s[p * 128 + c0], bb1 = b1s[p * 128 + c0 + 1];
                    float2 v0, v1;
                    v0.x = fmaxf(acc[i][jc][0] + bb0, 0.f);
                    v0.y = fmaxf(acc[i][jc][1] + bb1, 0.f);
                    v1.x = fmaxf(acc[i][jc][2] + bb0, 0.f);
                    v1.y = fmaxf(acc[i][jc][3] + bb1, 0.f);
                    *(float2*)(hbuf + (size_t)r0 * HPITCH + c0) = v0;
                    *(float2*)(hbuf + (size_t)(r0 + 8) * HPITCH + c0) = v1;
                }
            }
            MEMBAR_CTA();
            BAR_ARRIVE(BHFULL);
        }
    } else {
        // ========== PRODUCERS: 4 warps — deep-pipelined staging + layer 2 ==========
        const int ptid = tid - 128;
        const float* xb = x + (size_t)rowBase * DIN + m * NH;

        auto bufaddr = [&](int s) { return sb + (uint32_t)s * STAGE_STRIDE; };

        // B: 8 cp16/thread per chunk
        auto stageB = [&](int g, uint32_t buf) {
            const int p2 = g >> 3, k0 = (g & 7) * 64;
            #pragma unroll
            for (int j = 0; j < 8; j++) {
                int f = ptid + j * 128;
                int br = f >> 3, c16 = f & 7;
                const __half* src = g_w1h
                    + ((size_t)(m * 512 + p2 * 128 + br) * 512 + k0 + c16 * 8);
                cp16(buf + T_B + (uint32_t)br * 144u + (uint32_t)c16 * 16u, src);
            }
            cp_commit();
        };
        // A: 16 float4 LDG -> cvt to fp16 pairs in regs
        auto loadcvtA = [&](int g, uint2* av) {
            const int k0 = (g & 7) * 64;
            #pragma unroll
            for (int j = 0; j < 16; j++) {
                int f = ptid + j * 128;
                int row = f >> 4, kq = f & 15;
                float4 v = *(const float4*)(xb + (size_t)row * DIN + k0 + kq * 4);
                uint32_t p01, p23;
                cvt4(v, p01, p23);
                av[j] = make_uint2(p01, p23);
            }
        };
        auto stsA = [&](uint32_t buf, const uint2* av) {
            #pragma unroll
            for (int j = 0; j < 16; j++) {
                int f = ptid + j * 128;
                int row = f >> 4, kq = f & 15;
                sts8(buf + T_A + (uint32_t)row * 144u + (uint32_t)kq * 8u,
                     av[j].x, av[j].y);
            }
        };

        ull acc2[5] = {0, 0, 0, 0, 0};
        auto layer2 = [&](int pp) {
            BAR_SYNC(BHFULL);
            const float* hrow = hbuf + (size_t)ptid * HPITCH;
            #pragma unroll 4
            for (int cc = 0; cc < 128; cc += 4) {
                float4 h4 = *(const float4*)(hrow + cc);
                float hv[4] = {h4.x, h4.y, h4.z, h4.w};
                #pragma unroll
                for (int u = 0; u < 4; u++) {
                    ull hp = packdup(hv[u]);
                    const ull* wp = (const ull*)(w2s + (size_t)(pp * 128 + cc + u) * 12);
                    fma2(acc2[0], hp, wp[0]);
                    fma2(acc2[1], hp, wp[1]);
                    fma2(acc2[2], hp, wp[2]);
                    fma2(acc2[3], hp, wp[3]);
                    fma2(acc2[4], hp, wp[4]);
                }
            }
            BAR_ARRIVE(BHEMPTY);
        };

        BAR_ARRIVE(BHEMPTY);   // hbuf starts empty

        uint2 avb[2][16];
        // prologue: fill buffers 0,1 completely; prefetch A chunk 2
        stageB(0, bufaddr(0));
        loadcvtA(0, avb[0]); stsA(bufaddr(0), avb[0]);
        stageB(1, bufaddr(1));
        loadcvtA(1, avb[1]); stsA(bufaddr(1), avb[1]);
        loadcvtA(2, avb[0]);

        for (int g = 0; g < 32; g++) {
            if (g < 31) cp_wait1(); else cp_wait0();   // B(g) complete
            MEMBAR_CTA();
            BAR_ARRIVE(BFULL(g % 3));
            if (g + 2 <= 31) {
                const int s = (g + 2) % 3;
                if (g + 2 >= 3) BAR_SYNC(BEMPTY(s));
                stageB(g + 2, bufaddr(s));
                stsA(bufaddr(s), avb[g & 1]);          // chunk g+2 lives in slot g&1
                if (g + 3 <= 31) loadcvtA(g + 3, avb[(g + 1) & 1]);
            }
            if ((g & 7) == 1 && g >= 9) layer2((g >> 3) - 1);
        }
        layer2(3);

        float* yp = y + (size_t)(rowBase + ptid) * (NM * NOUT) + m * NOUT;
        #pragma unroll
        for (int q5 = 0; q5 < 5; q5++) {
            float2 v;
            v.x = __uint_as_float((uint32_t)(acc2[q5] & 0xffffffffu)) + b2[m * NOUT + 2 * q5];
            v.y = __uint_as_float((uint32_t)(acc2[q5] >> 32)) + b2[m * NOUT + 2 * q5 + 1];
            ((float2*)yp)[q5] = v;
        }
    }
}

extern "C" void kernel_launch(void* const* d_in, const int* in_sizes, int n_in,
                              void* d_out, int out_size) {
    const float* x  = (const float*)d_in[0];
    const float* W1 = (const float*)d_in[1];
    const float* b1 = (const float*)d_in[2];
    const float* W2 = (const float*)d_in[3];
    const float* b2 = (const float*)d_in[4];
    float* y = (float*)d_out;

    cvt_w1<<<2048, 256>>>(W1);

    cudaFuncSetAttribute(fused_f16,
                         cudaFuncAttributeMaxDynamicSharedMemorySize, SMEM_TOTAL);
    dim3 grid(8192 / 128, NM);   // 512 CTAs
    fused_f16<<<grid, 256, SMEM_TOTAL>>>(x, b1, W2, b2, y);
}

// round 10
// speedup vs baseline: 1.2632x; 1.2632x over previous
#include <cuda_runtime.h>
#include <cuda_fp16.h>
#include <cstdint>

typedef unsigned long long ull;

#define DIN   4096
#define NM    8
#define NH    512
#define NOUT  10

// fp16 pre-converted W1 diagonal blocks: [m][512 rows][512 k]
__device__ __half g_w1h[8u * 512u * 512u];

// ---- dynamic smem layout (bytes): 2-deep ring, 64-k chunks ----
// per stage: A 128*144 (18432) + B 256*144 (36864) = 55296
#define STAGE_STRIDE 55296u
#define T_A          0u
#define T_B          18432u
#define OFF_HBUF     110592u     // 128 * 132 * 4 = 67584
#define HPITCH       132
#define OFF_W2       178176u     // 512*12*4 = 24576
#define OFF_B1       202752u     // 2048
#define SMEM_TOTAL   204800u

static __device__ __forceinline__ uint32_t smem_u32(const void* p) {
    uint32_t a;
    asm("{ .reg .u64 t; cvta.to.shared.u64 t, %1; cvt.u32.u64 %0, t; }"
        : "=r"(a) : "l"(p));
    return a;
}
static __device__ __forceinline__ void ldsm4(uint32_t* r, uint32_t addr) {
    asm volatile("ldmatrix.sync.aligned.m8n8.x4.shared.b16 {%0,%1,%2,%3}, [%4];"
                 : "=r"(r[0]), "=r"(r[1]), "=r"(r[2]), "=r"(r[3]) : "r"(addr));
}
static __device__ __forceinline__ void mma16816f(float* d, const uint32_t* a,
                                                 uint32_t b0, uint32_t b1) {
    asm volatile("mma.sync.aligned.m16n8k16.row.col.f32.f16.f16.f32 "
                 "{%0,%1,%2,%3}, {%4,%5,%6,%7}, {%8,%9}, {%0,%1,%2,%3};"
                 : "+f"(d[0]), "+f"(d[1]), "+f"(d[2]), "+f"(d[3])
                 : "r"(a[0]), "r"(a[1]), "r"(a[2]), "r"(a[3]), "r"(b0), "r"(b1));
}
static __device__ __forceinline__ void cp16(uint32_t dst, const void* src) {
    asm volatile("cp.async.cg.shared.global [%0], [%1], 16;"
                 :: "r"(dst), "l"(src) : "memory");
}
static __device__ __forceinline__ void cp_commit() {
    asm volatile("cp.async.commit_group;" ::: "memory");
}
static __device__ __forceinline__ void cp_wait0() {
    asm volatile("cp.async.wait_group 0;" ::: "memory");
}
static __device__ __forceinline__ ull packdup(float v) {
    ull r;
    asm("mov.b64 %0, {%1, %1};" : "=l"(r) : "r"(__float_as_uint(v)));
    return r;
}
static __device__ __forceinline__ void fma2(ull& d, ull a, ull b) {
    asm("fma.rn.f32x2 %0, %1, %2, %0;" : "+l"(d) : "l"(a), "l"(b));
}
static __device__ __forceinline__ ull add2(ull a, ull b) {
    ull r;
    asm("add.rn.f32x2 %0, %1, %2;" : "=l"(r) : "l"(a), "l"(b));
    return r;
}
static __device__ __forceinline__ void sts8(uint32_t addr, uint32_t a, uint32_t b) {
    asm volatile("st.shared.v2.b32 [%0], {%1,%2};" :: "r"(addr), "r"(a), "r"(b) : "memory");
}
static __device__ __forceinline__ void cvt4(float4 v, uint32_t& p01, uint32_t& p23) {
    __half2 a = __floats2half2_rn(v.x, v.y);
    __half2 b = __floats2half2_rn(v.z, v.w);
    p01 = *(uint32_t*)&a;
    p23 = *(uint32_t*)&b;
}

// ---------------- pre-pass: W1 diag blocks -> fp16 ----------------
__global__ __launch_bounds__(256)
void cvt_w1(const float* __restrict__ W1) {
    int g = blockIdx.x * 256 + threadIdx.x;
    int m = g >> 16;
    int rem = g & 65535;
    int r = rem >> 7;
    int c4 = rem & 127;
    float4 v = *(const float4*)(W1 + (size_t)(m * 512 + r) * DIN + m * 512 + c4 * 4);
    uint32_t p01, p23;
    cvt4(v, p01, p23);
    *(uint2*)(g_w1h + ((size_t)(m * 512 + r) * 512 + c4 * 4)) = make_uint2(p01, p23);
}

// -------- homogeneous fused kernel: 8 warps, all issue MMA --------
__global__ __launch_bounds__(256, 1)
void fused_f16h(const float* __restrict__ x,  const float* __restrict__ b1,
                const float* __restrict__ W2, const float* __restrict__ b2,
                float* __restrict__ y) {
    extern __shared__ char smem[];
    const uint32_t sb = smem_u32(smem);
    const int tid  = threadIdx.x;
    const int wid  = tid >> 5;
    const int lane = tid & 31;
    const int m       = blockIdx.y;
    const int rowBase = blockIdx.x * 128;

    float* w2s  = (float*)(smem + OFF_W2);
    float* b1s  = (float*)(smem + OFF_B1);
    float* hbuf = (float*)(smem + OFF_HBUF);

    for (int i = tid; i < NH; i += 256) b1s[i] = b1[m * NH + i];
    for (int idx = tid; idx < NH * 12; idx += 256) {
        int c = idx / 12, o = idx - c * 12;
        w2s[idx] = (o < NOUT) ? W2[(size_t)(m * NOUT + o) * DIN + m * NH + c] : 0.f;
    }
    __syncthreads();

    const int wm = wid & 1;            // 2 x 64 rows
    const int wn = wid >> 1;           // 4 x 64 cols (within 256-wide pass tile)
    const uint32_t lmoff = (uint32_t)(lane & 15) * 144u + (uint32_t)(lane >> 4) * 16u;
    const float* xb = x + (size_t)rowBase * DIN + m * NH;

    // A: 8 float4 per thread per 64-k chunk
    float4 av[8];
    auto loadA = [&](int g) {
        const int k0 = g * 64;
        #pragma unroll
        for (int j = 0; j < 8; j++) {
            int f = tid + j * 256;
            int row = f >> 4, kq = f & 15;
            av[j] = *(const float4*)(xb + (size_t)row * DIN + k0 + kq * 4);
        }
    };
    auto stsA = [&](uint32_t buf) {
        #pragma unroll
        for (int j = 0; j < 8; j++) {
            int f = tid + j * 256;
            int row = f >> 4, kq = f & 15;
            uint32_t p01, p23;
            cvt4(av[j], p01, p23);
            sts8(buf + T_A + (uint32_t)row * 144u + (uint32_t)kq * 8u, p01, p23);
        }
    };
    // B: 8 cp16 per thread per chunk (256 W1 rows x 64 k)
    auto stageB = [&](int p, int g, uint32_t buf) {
        const int k0 = g * 64;
        #pragma unroll
        for (int j = 0; j < 8; j++) {
            int f = tid + j * 256;
            int br = f >> 3, c16 = f & 7;
            const __half* src = g_w1h
                + ((size_t)(m * 512 + p * 256 + br) * 512 + k0 + c16 * 8);
            cp16(buf + T_B + (uint32_t)br * 144u + (uint32_t)c16 * 16u, src);
        }
        cp_commit();
    };

    ull acc2[5] = {0, 0, 0, 0, 0};

    for (int p = 0; p < 2; p++) {
        float acc[4][8][4];
        #pragma unroll
        for (int i = 0; i < 4; i++)
            #pragma unroll
            for (int j = 0; j < 8; j++)
                #pragma unroll
                for (int q = 0; q < 4; q++) acc[i][j][q] = 0.f;

        // prologue: stage chunk 0 into buffer 0
        stageB(p, 0, sb);
        loadA(0);
        stsA(sb);
        cp_wait0();
        __syncthreads();

        for (int g = 0; g < 8; g++) {
            const uint32_t base = sb + (uint32_t)(g & 1) * STAGE_STRIDE;
            const uint32_t nbuf = sb + (uint32_t)((g + 1) & 1) * STAGE_STRIDE;
            if (g < 7) {
                loadA(g + 1);            // LDG issues early, lands during MMA
                stageB(p, g + 1, nbuf);  // cp.async issues early
            }
            // ---- MMA on chunk g ----
            #pragma unroll
            for (int ks = 0; ks < 4; ks++) {
                uint32_t af[4][4];
                #pragma unroll
                for (int i = 0; i < 4; i++) {
                    uint32_t off = (uint32_t)(wm * 64 + i * 16) * 144u + ks * 32u + lmoff;
                    ldsm4(af[i], base + T_A + off);
                }
                #pragma unroll
                for (int jh = 0; jh < 2; jh++) {
                    uint32_t bf[4][2];
                    #pragma unroll
                    for (int jj = 0; jj < 2; jj++) {
                        uint32_t off = (uint32_t)(wn * 64 + jh * 32 + jj * 16) * 144u
                                     + ks * 32u + lmoff;
                        uint32_t rh[4];
                        ldsm4(rh, base + T_B + off);
                        bf[2 * jj][0] = rh[0];     bf[2 * jj][1] = rh[2];
                        bf[2 * jj + 1][0] = rh[1]; bf[2 * jj + 1][1] = rh[3];
                    }
                    #pragma unroll
                    for (int i = 0; i < 4; i++)
                        #pragma unroll
                        for (int j = 0; j < 4; j++)
                            mma16816f(acc[i][jh * 4 + j], af[i], bf[j][0], bf[j][1]);
                }
            }
            if (g < 7) {
                stsA(nbuf);              // cvt + store prefetched A
                cp_wait0();              // B(g+1) landed
            }
            __syncthreads();
        }

        // ---- epilogue + fused layer 2, in two 128-col halves ----
        #pragma unroll
        for (int h2 = 0; h2 < 2; h2++) {
            if ((wn >> 1) == h2) {
                #pragma unroll
                for (int i = 0; i < 4; i++) {
                    int r0 = wm * 64 + i * 16 + (lane >> 2);
                    #pragma unroll
                    for (int jc = 0; jc < 8; jc++) {
                        int c0 = (wn & 1) * 64 + jc * 8 + 2 * (lane & 3);
                        int gc = p * 256 + h2 * 128 + c0;
                        float bb0 = b1s[gc], bb1 = b1s[gc + 1];
                        float2 v0, v1;
                        v0.x = fmaxf(acc[i][jc][0] + bb0, 0.f);
                        v0.y = fmaxf(acc[i][jc][1] + bb1, 0.f);
                        v1.x = fmaxf(acc[i][jc][2] + bb0, 0.f);
                        v1.y = fmaxf(acc[i][jc][3] + bb1, 0.f);
                        *(float2*)(hbuf + (size_t)r0 * HPITCH + c0) = v0;
                        *(float2*)(hbuf + (size_t)(r0 + 8) * HPITCH + c0) = v1;
                    }
                }
            }
            __syncthreads();
            // layer 2: 2 threads per row (even/odd cols)
            {
                const int row = tid >> 1;
                const int par = tid & 1;
                const float* hrow = hbuf + (size_t)row * HPITCH;
                #pragma unroll 8
                for (int cc = 0; cc < 64; cc++) {
                    int lc = par + 2 * cc;
                    ull hp = packdup(hrow[lc]);
                    int gc = p * 256 + h2 * 128 + lc;
                    const ull* wp = (const ull*)(w2s + (size_t)gc * 12);
                    fma2(acc2[0], hp, wp[0]);
                    fma2(acc2[1], hp, wp[1]);
                    fma2(acc2[2], hp, wp[2]);
                    fma2(acc2[3], hp, wp[3]);
                    fma2(acc2[4], hp, wp[4]);
                }
            }
            __syncthreads();
        }
    }

    // ---- reduce even/odd partner, add b2, store ----
    #pragma unroll
    for (int q5 = 0; q5 < 5; q5++)
        acc2[q5] = add2(acc2[q5], __shfl_xor_sync(0xffffffffu, acc2[q5], 1));
    if ((tid & 1) == 0) {
        const int row = tid >> 1;
        float* yp = y + (size_t)(rowBase + row) * (NM * NOUT) + m * NOUT;
        #pragma unroll
        for (int q5 = 0; q5 < 5; q5++) {
            float2 v;
            v.x = __uint_as_float((uint32_t)(acc2[q5] & 0xffffffffu)) + b2[m * NOUT + 2 * q5];
            v.y = __uint_as_float((uint32_t)(acc2[q5] >> 32)) + b2[m * NOUT + 2 * q5 + 1];
            ((float2*)yp)[q5] = v;
        }
    }
}

extern "C" void kernel_launch(void* const* d_in, const int* in_sizes, int n_in,
                              void* d_out, int out_size) {
    const float* x  = (const float*)d_in[0];
    const float* W1 = (const float*)d_in[1];
    const float* b1 = (const float*)d_in[2];
    const float* W2 = (const float*)d_in[3];
    const float* b2 = (const float*)d_in[4];
    float* y = (float*)d_out;

    cvt_w1<<<2048, 256>>>(W1);

    cudaFuncSetAttribute(fused_f16h,
                         cudaFuncAttributeMaxDynamicSharedMemorySize, SMEM_TOTAL);
    dim3 grid(8192 / 128, NM);   // 512 CTAs
    fused_f16h<<<grid, 256, SMEM_TOTAL>>>(x, b1, W2, b2, y);
}